// round 5
// baseline (speedup 1.0000x reference)
#include <cuda_runtime.h>

#define BB 8
#define SS 2048
#define DIN 1024
#define DOUT 64

// Scratch (device globals: no allocation allowed)
__device__ float g_q[BB * SS * DOUT];
__device__ float g_k[BB * SS * DOUT];
__device__ float g_v[BB * SS * DOUT];
__device__ unsigned char g_mask[BB * SS];

// ---------------------------------------------------------------------------
// Mask normalization: detect dtype (bool/uint8 vs int32 vs float32) from byte
// patterns, expand to g_mask[i] in {0,1}. Single tiny block.
// ---------------------------------------------------------------------------
__global__ void mask_normalize(const unsigned char* __restrict__ p) {
    __shared__ int s_off;   // nonzero bytes at pos % 4 != 0
    __shared__ int s_al;    // nonzero bytes at pos % 4 == 0
    int t = threadIdx.x;
    if (t == 0) { s_off = 0; s_al = 0; }
    __syncthreads();

    int loc_off = 0, loc_al = 0;
    for (int i = t; i < BB * SS; i += 256) {   // first 16384 bytes: in-bounds for all dtypes
        unsigned char v = p[i];
        if (v) { if (i & 3) loc_off++; else loc_al++; }
    }
    if (loc_off) atomicAdd(&s_off, loc_off);
    if (loc_al)  atomicAdd(&s_al, loc_al);
    __syncthreads();

    int kind = 0;                         // 0 = 1-byte bool/uint8
    if (s_off == 0 && s_al > 0) kind = 1; // int32: value in low byte only
    else if (s_al == 0 && s_off > 0) kind = 2; // float32: 1.0f = 00 00 80 3f

    for (int i = t; i < BB * SS; i += 256) {
        unsigned char m;
        if (kind == 1)      m = (((const int*)(const void*)p)[i] != 0);
        else if (kind == 2) m = (((const float*)(const void*)p)[i] != 0.0f);
        else                m = (p[i] != 0);
        g_mask[i] = m;
    }
}

// ---------------------------------------------------------------------------
// Fused QKV projection GEMM with register double buffering:
//   {q,k,v}[M=16384, 64] = seq[16384,1024] @ W{q,k,v}[1024,64] + b{q,k,v}
// BM=64, BN=64, BK=16, 256 threads, 4x4 register tile per thread per output.
// A tile loaded once from gmem, reused for all three weight matrices.
// Next iteration's gmem loads are issued before the FMA loop so DRAM/L2
// latency overlaps with compute.
// ---------------------------------------------------------------------------
__global__ void __launch_bounds__(256) proj_qkv(
    const float* __restrict__ A,
    const float* __restrict__ Wq, const float* __restrict__ bq,
    const float* __restrict__ Wk, const float* __restrict__ bk,
    const float* __restrict__ Wv, const float* __restrict__ bv)
{
    __shared__ float As [16][68];   // [k][m-row]
    __shared__ float Bsq[16][68];   // [k][n-col]
    __shared__ float Bsk[16][68];
    __shared__ float Bsv[16][68];

    int tid = threadIdx.x;
    int tx = tid & 15, ty = tid >> 4;
    int m0 = blockIdx.x * 64;

    int arow = tid >> 2;           // 0..63
    int acol = (tid & 3) << 2;     // 0,4,8,12
    int brow = tid >> 4;           // 0..15
    int bcol = (tid & 15) << 2;    // 0..60

    const float* Aptr  = A  + (size_t)(m0 + arow) * DIN + acol;
    const float* Wqptr = Wq + (size_t)brow * DOUT + bcol;
    const float* Wkptr = Wk + (size_t)brow * DOUT + bcol;
    const float* Wvptr = Wv + (size_t)brow * DOUT + bcol;

    float accq[4][4] = {}, acck[4][4] = {}, accv[4][4] = {};

    // Prologue: load first tile into registers
    float4 av  = *(const float4*)(Aptr);
    float4 bq4 = *(const float4*)(Wqptr);
    float4 bk4 = *(const float4*)(Wkptr);
    float4 bv4 = *(const float4*)(Wvptr);

    for (int k0 = 0; k0 < DIN; k0 += 16) {
        // Stage current registers -> smem
        As[acol + 0][arow] = av.x;
        As[acol + 1][arow] = av.y;
        As[acol + 2][arow] = av.z;
        As[acol + 3][arow] = av.w;
        *(float4*)&Bsq[brow][bcol] = bq4;
        *(float4*)&Bsk[brow][bcol] = bk4;
        *(float4*)&Bsv[brow][bcol] = bv4;
        __syncthreads();

        // Prefetch next tile (overlaps with FMA loop below)
        if (k0 + 16 < DIN) {
            av  = *(const float4*)(Aptr + k0 + 16);
            size_t woff = (size_t)(k0 + 16) * DOUT;
            bq4 = *(const float4*)(Wqptr + woff);
            bk4 = *(const float4*)(Wkptr + woff);
            bv4 = *(const float4*)(Wvptr + woff);
        }

        #pragma unroll
        for (int k = 0; k < 16; k++) {
            float4 a4 = *(const float4*)&As[k][ty << 2];
            float aa[4] = {a4.x, a4.y, a4.z, a4.w};
            float4 q4 = *(const float4*)&Bsq[k][tx << 2];
            float4 k4 = *(const float4*)&Bsk[k][tx << 2];
            float4 v4 = *(const float4*)&Bsv[k][tx << 2];
            float qq[4] = {q4.x, q4.y, q4.z, q4.w};
            float kk[4] = {k4.x, k4.y, k4.z, k4.w};
            float vv[4] = {v4.x, v4.y, v4.z, v4.w};
            #pragma unroll
            for (int i = 0; i < 4; i++) {
                #pragma unroll
                for (int j = 0; j < 4; j++) {
                    accq[i][j] += aa[i] * qq[j];
                    acck[i][j] += aa[i] * kk[j];
                    accv[i][j] += aa[i] * vv[j];
                }
            }
        }
        __syncthreads();
    }

    float4 bqv = *(const float4*)(bq + (tx << 2));
    float4 bkv = *(const float4*)(bk + (tx << 2));
    float4 bvv = *(const float4*)(bv + (tx << 2));
    #pragma unroll
    for (int i = 0; i < 4; i++) {
        size_t row = (size_t)(m0 + (ty << 2) + i) * DOUT + (tx << 2);
        float4 oq = { accq[i][0] + bqv.x, accq[i][1] + bqv.y,
                      accq[i][2] + bqv.z, accq[i][3] + bqv.w };
        float4 ok = { acck[i][0] + bkv.x, acck[i][1] + bkv.y,
                      acck[i][2] + bkv.z, acck[i][3] + bkv.w };
        float4 ov = { accv[i][0] + bvv.x, accv[i][1] + bvv.y,
                      accv[i][2] + bvv.z, accv[i][3] + bvv.w };
        *(float4*)&g_q[row] = oq;
        *(float4*)&g_k[row] = ok;
        *(float4*)&g_v[row] = ov;
    }
}

// ---------------------------------------------------------------------------
// Fused flash attention, fp32. Block = 64 queries of one batch, 256 threads.
// Key chunks of 64. Dynamic smem layout (stride 68 floats, 16B aligned rows):
//   Qs[64][68]  (pre-scaled by 1/sqrt(S))
//   Kst[64][68] (d-major: Kst[d][key])
//   Vs[64][68]  (key-major)
//   Ps[64][68]
//   mrow[64], lrow[64]
// ---------------------------------------------------------------------------
#define STR 68
#define ATT_SMEM_FLOATS (4 * 64 * STR + 128)
#define ATT_SMEM_BYTES (ATT_SMEM_FLOATS * 4)

__global__ void __launch_bounds__(256) attn_kernel(float* __restrict__ out)
{
    extern __shared__ float sm[];
    float* Qs   = sm;
    float* Kst  = sm + 64 * STR;
    float* Vs   = sm + 2 * 64 * STR;
    float* Ps   = sm + 3 * 64 * STR;
    float* mrow = sm + 4 * 64 * STR;
    float* lrow = mrow + 64;
    __shared__ unsigned char maskS[64];

    int b  = blockIdx.y;
    int q0 = blockIdx.x * 64;
    int tid = threadIdx.x;
    int tx = tid & 15, ty = tid >> 4;

    const float scale = rsqrtf((float)SS);   // reference divides by sqrt(S)

    // Load Q tile (scaled). thread: row tid>>2, 16 cols starting (tid&3)*16
    {
        int r = tid >> 2;
        int cb = (tid & 3) << 4;
        const float* gq = g_q + (size_t)(b * SS + q0 + r) * DOUT;
        #pragma unroll
        for (int j = 0; j < 4; j++) {
            float4 v = *(const float4*)(gq + cb + 4 * j);
            v.x *= scale; v.y *= scale; v.z *= scale; v.w *= scale;
            *(float4*)&Qs[r * STR + cb + 4 * j] = v;
        }
    }
    if (tid < 64) { mrow[tid] = -1e30f; lrow[tid] = 0.0f; }

    float o[4][4] = {};

    for (int kb0 = 0; kb0 < SS; kb0 += 64) {
        __syncthreads();   // protect Kst/Vs/Ps from previous chunk readers

        // Load K (transposed to d-major) and V (key-major)
        {
            int r = tid >> 2;              // local key 0..63
            int cb = (tid & 3) << 4;       // d base
            const float* gk = g_k + (size_t)(b * SS + kb0 + r) * DOUT;
            const float* gv = g_v + (size_t)(b * SS + kb0 + r) * DOUT;
            #pragma unroll
            for (int j = 0; j < 4; j++) {
                int d = cb + 4 * j;
                float4 kv = *(const float4*)(gk + d);
                Kst[(d + 0) * STR + r] = kv.x;
                Kst[(d + 1) * STR + r] = kv.y;
                Kst[(d + 2) * STR + r] = kv.z;
                Kst[(d + 3) * STR + r] = kv.w;
                *(float4*)&Vs[r * STR + d] = *(const float4*)(gv + d);
            }
            if (tid < 64) maskS[tid] = g_mask[b * SS + kb0 + tid];
        }
        __syncthreads();

        // S = Q K^T for this thread's 4 rows x 4 cols
        float acc[4][4] = {};
        #pragma unroll 4
        for (int d = 0; d < 64; d += 4) {
            float qv[4][4];
            #pragma unroll
            for (int i = 0; i < 4; i++) {
                float4 q4 = *(const float4*)&Qs[((ty << 2) + i) * STR + d];
                qv[i][0] = q4.x; qv[i][1] = q4.y; qv[i][2] = q4.z; qv[i][3] = q4.w;
            }
            float kv[4][4];
            #pragma unroll
            for (int dd = 0; dd < 4; dd++) {
                float4 k4 = *(const float4*)&Kst[(d + dd) * STR + (tx << 2)];
                kv[dd][0] = k4.x; kv[dd][1] = k4.y; kv[dd][2] = k4.z; kv[dd][3] = k4.w;
            }
            #pragma unroll
            for (int i = 0; i < 4; i++)
                #pragma unroll
                for (int j = 0; j < 4; j++)
                    acc[i][j] += qv[i][0] * kv[0][j] + qv[i][1] * kv[1][j]
                               + qv[i][2] * kv[2][j] + qv[i][3] * kv[3][j];
        }

        // Mask (column-wise, matches reference where(mask[:,None,:], -1e9, .))
        #pragma unroll
        for (int j = 0; j < 4; j++) {
            if (maskS[(tx << 2) + j]) {
                #pragma unroll
                for (int i = 0; i < 4; i++) acc[i][j] = -1e9f;
            }
        }

        // Online softmax per row (row owned by one 16-lane group)
        float fct[4];
        #pragma unroll
        for (int i = 0; i < 4; i++) {
            int r = (ty << 2) + i;
            float rm = fmaxf(fmaxf(acc[i][0], acc[i][1]), fmaxf(acc[i][2], acc[i][3]));
            #pragma unroll
            for (int off = 8; off > 0; off >>= 1)
                rm = fmaxf(rm, __shfl_xor_sync(0xffffffffu, rm, off));
            float mold = mrow[r];
            float mnew = fmaxf(mold, rm);
            fct[i] = __expf(mold - mnew);
            float rs = 0.0f;
            #pragma unroll
            for (int j = 0; j < 4; j++) {
                float pv = __expf(acc[i][j] - mnew);
                Ps[r * STR + (tx << 2) + j] = pv;
                rs += pv;
            }
            #pragma unroll
            for (int off = 8; off > 0; off >>= 1)
                rs += __shfl_xor_sync(0xffffffffu, rs, off);
            if (tx == 0) {
                mrow[r] = mnew;
                lrow[r] = lrow[r] * fct[i] + rs;
            }
        }
        __syncwarp();

        // O = O*fct + P V
        #pragma unroll
        for (int i = 0; i < 4; i++)
            #pragma unroll
            for (int j = 0; j < 4; j++) o[i][j] *= fct[i];

        #pragma unroll 4
        for (int k = 0; k < 64; k += 4) {
            float pv[4][4];
            #pragma unroll
            for (int i = 0; i < 4; i++) {
                float4 p4 = *(const float4*)&Ps[((ty << 2) + i) * STR + k];
                pv[i][0] = p4.x; pv[i][1] = p4.y; pv[i][2] = p4.z; pv[i][3] = p4.w;
            }
            float vv[4][4];
            #pragma unroll
            for (int kk = 0; kk < 4; kk++) {
                float4 v4 = *(const float4*)&Vs[(k + kk) * STR + (tx << 2)];
                vv[kk][0] = v4.x; vv[kk][1] = v4.y; vv[kk][2] = v4.z; vv[kk][3] = v4.w;
            }
            #pragma unroll
            for (int i = 0; i < 4; i++)
                #pragma unroll
                for (int j = 0; j < 4; j++)
                    o[i][j] += pv[i][0] * vv[0][j] + pv[i][1] * vv[1][j]
                             + pv[i][2] * vv[2][j] + pv[i][3] * vv[3][j];
        }
    }

    __syncwarp();
    #pragma unroll
    for (int i = 0; i < 4; i++) {
        int r = (ty << 2) + i;
        float linv = 1.0f / lrow[r];
        float4 ov;
        ov.x = o[i][0] * linv;
        ov.y = o[i][1] * linv;
        ov.z = o[i][2] * linv;
        ov.w = o[i][3] * linv;
        *(float4*)&out[(size_t)(b * SS + q0 + r) * DOUT + (tx << 2)] = ov;
    }
}

// ---------------------------------------------------------------------------
extern "C" void kernel_launch(void* const* d_in, const int* in_sizes, int n_in,
                              void* d_out, int out_size)
{
    const float* seq = (const float*)d_in[0];
    const unsigned char* mask = (const unsigned char*)d_in[1];
    const float* Wq = (const float*)d_in[2];
    const float* bq = (const float*)d_in[3];
    const float* Wk = (const float*)d_in[4];
    const float* bk = (const float*)d_in[5];
    const float* Wv = (const float*)d_in[6];
    const float* bv = (const float*)d_in[7];
    float* out = (float*)d_out;

    mask_normalize<<<1, 256>>>(mask);

    proj_qkv<<<256, 256>>>(seq, Wq, bq, Wk, bk, Wv, bv);

    cudaFuncSetAttribute(attn_kernel, cudaFuncAttributeMaxDynamicSharedMemorySize,
                         ATT_SMEM_BYTES);
    attn_kernel<<<dim3(SS / 64, BB), 256, ATT_SMEM_BYTES>>>(out);
}

// round 12
// speedup vs baseline: 2.0795x; 2.0795x over previous
#include <cuda_runtime.h>
#include <cuda_bf16.h>
#include <cstdint>

#define BB 8
#define SS 2048
#define DIN 1024
#define DOUT 64

// Scratch (device globals: no allocation allowed)
__device__ float g_q[BB * SS * DOUT];
__device__ float g_k[BB * SS * DOUT];
__device__ float g_v[BB * SS * DOUT];
__device__ unsigned char g_mask[BB * SS];
// W transposed + bf16 hi/lo split: [w][n][k]
__device__ __align__(16) __nv_bfloat16 g_wh[3 * DOUT * DIN];
__device__ __align__(16) __nv_bfloat16 g_wl[3 * DOUT * DIN];

// ---------------------------------------------------------------------------
// Helpers
// ---------------------------------------------------------------------------
__device__ __forceinline__ uint32_t bpack(__nv_bfloat16 a, __nv_bfloat16 b) {
    return ((uint32_t)__bfloat16_as_ushort(b) << 16) | __bfloat16_as_ushort(a);
}

// mma.sync m16n8k16 row.col f32 += bf16*bf16 (baseline PTX ISA, sm_80+)
__device__ __forceinline__ void mma16816(float* c, const uint32_t* a, const uint32_t* b) {
    asm volatile(
        "mma.sync.aligned.m16n8k16.row.col.f32.bf16.bf16.f32 "
        "{%0,%1,%2,%3}, {%4,%5,%6,%7}, {%8,%9}, {%0,%1,%2,%3};"
        : "+f"(c[0]), "+f"(c[1]), "+f"(c[2]), "+f"(c[3])
        : "r"(a[0]), "r"(a[1]), "r"(a[2]), "r"(a[3]), "r"(b[0]), "r"(b[1]));
}

// exp(x) for x <= 0 on the FMA/ALU pipes (no MUFU). 2^(x*log2e) with
// magic-number rounding + degree-5 poly on f in [-0.5, 0.5]. rel err ~2e-6.
__device__ __forceinline__ float exp_fma(float x) {
    x = fmaxf(x, -87.0f);
    float t  = fmaf(x, 1.4426950408889634f, 12582912.0f);   // RN to integer
    float fi = t - 12582912.0f;
    float f  = fmaf(x, 1.4426950408889634f, -fi);           // frac in [-0.5,0.5]
    float p  = 0.0013333558f;
    p = fmaf(p, f, 0.0096181291f);
    p = fmaf(p, f, 0.0555041087f);
    p = fmaf(p, f, 0.2402265069f);
    p = fmaf(p, f, 0.6931471806f);
    p = fmaf(p, f, 1.0f);
    int ei = (__float_as_int(t) & 0x7FFFFF) - 0x400000;     // = round(x*log2e) <= 0
    return __int_as_float((ei + 127) << 23) * p;
}

// ---------------------------------------------------------------------------
// W prep: transpose + bf16 hi/lo split. g_wh/g_wl[w][n][k].
// ---------------------------------------------------------------------------
__global__ void w_convert(const float* __restrict__ Wq, const float* __restrict__ Wk,
                          const float* __restrict__ Wv) {
    int tot = 3 * DIN * DOUT;
    for (int i = blockIdx.x * blockDim.x + threadIdx.x; i < tot; i += gridDim.x * blockDim.x) {
        int w = i / (DIN * DOUT);
        int r = i - w * (DIN * DOUT);
        int k = r / DOUT, n = r % DOUT;
        const float* W = (w == 0) ? Wq : (w == 1) ? Wk : Wv;
        float x = W[r];
        __nv_bfloat16 h = __float2bfloat16(x);
        __nv_bfloat16 l = __float2bfloat16(x - __bfloat162float(h));
        g_wh[w * DIN * DOUT + n * DIN + k] = h;
        g_wl[w * DIN * DOUT + n * DIN + k] = l;
    }
}

// ---------------------------------------------------------------------------
// HMMA QKV projection (bf16x3 split). 128 CTAs x 256 thr, M_tile=128.
// CTA 0 folds in mask normalization.
// ---------------------------------------------------------------------------
#define ASTR 72
#define SM_AH 0
#define SM_AL (128 * ASTR * 2)
#define SM_W  (2 * 128 * ASTR * 2)
#define SM_BIAS (SM_W + 6 * 64 * ASTR * 2)
#define PJ_SMEM (SM_BIAS + 768)

__global__ void __launch_bounds__(256) proj_mma(
    const float* __restrict__ A, const unsigned char* __restrict__ maskp,
    const float* __restrict__ bq, const float* __restrict__ bk, const float* __restrict__ bv)
{
    extern __shared__ unsigned char smem[];
    __nv_bfloat16* AH = (__nv_bfloat16*)(smem + SM_AH);
    __nv_bfloat16* AL = (__nv_bfloat16*)(smem + SM_AL);
    float* biasS = (float*)(smem + SM_BIAS);

    int tid = threadIdx.x, wid = tid >> 5, lane = tid & 31;
    int g = lane >> 2, t = lane & 3;
    int m0 = blockIdx.x * 128;
    int r0 = wid * 16;

    if (blockIdx.x == 0) {
        __shared__ int s_off, s_al;
        if (tid == 0) { s_off = 0; s_al = 0; }
        __syncthreads();
        int lo = 0, la = 0;
        for (int i = tid; i < BB * SS; i += 256) {
            unsigned char v = maskp[i];
            if (v) { if (i & 3) lo++; else la++; }
        }
        if (lo) atomicAdd(&s_off, lo);
        if (la) atomicAdd(&s_al, la);
        __syncthreads();
        int kind = 0;
        if (s_off == 0 && s_al > 0) kind = 1;
        else if (s_al == 0 && s_off > 0) kind = 2;
        for (int i = tid; i < BB * SS; i += 256) {
            unsigned char m;
            if (kind == 1)      m = (((const int*)(const void*)maskp)[i] != 0);
            else if (kind == 2) m = (((const float*)(const void*)maskp)[i] != 0.0f);
            else                m = (maskp[i] != 0);
            g_mask[i] = m;
        }
    }

    if (tid < 64) {
        biasS[tid]       = bq[tid];
        biasS[tid + 64]  = bk[tid];
        biasS[tid + 128] = bv[tid];
    }

    float acc[3][8][4];
    #pragma unroll
    for (int w = 0; w < 3; w++)
        #pragma unroll
        for (int nb = 0; nb < 8; nb++)
            #pragma unroll
            for (int i = 0; i < 4; i++) acc[w][nb][i] = 0.0f;

    for (int c = 0; c < 16; c++) {
        int k0 = c * 64;
        __syncthreads();

        #pragma unroll
        for (int it = 0; it < 8; it++) {
            int idx = it * 256 + tid;
            int row = idx >> 4;
            int col = (idx & 15) << 2;
            float4 v = *(const float4*)(A + (size_t)(m0 + row) * DIN + k0 + col);
            __nv_bfloat16 h0 = __float2bfloat16(v.x), h1 = __float2bfloat16(v.y);
            __nv_bfloat16 h2 = __float2bfloat16(v.z), h3 = __float2bfloat16(v.w);
            __nv_bfloat16 l0 = __float2bfloat16(v.x - __bfloat162float(h0));
            __nv_bfloat16 l1 = __float2bfloat16(v.y - __bfloat162float(h1));
            __nv_bfloat16 l2 = __float2bfloat16(v.z - __bfloat162float(h2));
            __nv_bfloat16 l3 = __float2bfloat16(v.w - __bfloat162float(h3));
            uint2 hv = { bpack(h0, h1), bpack(h2, h3) };
            uint2 lv = { bpack(l0, l1), bpack(l2, l3) };
            *(uint2*)(AH + row * ASTR + col) = hv;
            *(uint2*)(AL + row * ASTR + col) = lv;
        }

        #pragma unroll
        for (int it = 0; it < 24; it++) {
            int i = it * 256 + tid;
            int tile = i >> 10;
            int word = i & 1023;
            int n = word >> 4;
            int kk = (word & 15) << 2;
            const __nv_bfloat16* src = (tile & 1) ? g_wl : g_wh;
            uint2 d = *(const uint2*)(src + (size_t)(tile >> 1) * (DIN * DOUT) + n * DIN + k0 + kk);
            *(uint2*)((__nv_bfloat16*)(smem + SM_W) + tile * (64 * ASTR) + n * ASTR + kk) = d;
        }
        __syncthreads();

        #pragma unroll
        for (int ks = 0; ks < 4; ks++) {
            int kb = ks * 16;
            uint32_t ah[4], al[4];
            ah[0] = *(const uint32_t*)(AH + (r0 + g)     * ASTR + kb + t * 2);
            ah[1] = *(const uint32_t*)(AH + (r0 + g + 8) * ASTR + kb + t * 2);
            ah[2] = *(const uint32_t*)(AH + (r0 + g)     * ASTR + kb + t * 2 + 8);
            ah[3] = *(const uint32_t*)(AH + (r0 + g + 8) * ASTR + kb + t * 2 + 8);
            al[0] = *(const uint32_t*)(AL + (r0 + g)     * ASTR + kb + t * 2);
            al[1] = *(const uint32_t*)(AL + (r0 + g + 8) * ASTR + kb + t * 2);
            al[2] = *(const uint32_t*)(AL + (r0 + g)     * ASTR + kb + t * 2 + 8);
            al[3] = *(const uint32_t*)(AL + (r0 + g + 8) * ASTR + kb + t * 2 + 8);

            #pragma unroll
            for (int w = 0; w < 3; w++) {
                const __nv_bfloat16* WH = (__nv_bfloat16*)(smem + SM_W) + (w * 2)     * (64 * ASTR);
                const __nv_bfloat16* WL = (__nv_bfloat16*)(smem + SM_W) + (w * 2 + 1) * (64 * ASTR);
                #pragma unroll
                for (int nb = 0; nb < 8; nb++) {
                    int n = nb * 8 + g;
                    uint32_t bh[2], bl[2];
                    bh[0] = *(const uint32_t*)(WH + n * ASTR + kb + t * 2);
                    bh[1] = *(const uint32_t*)(WH + n * ASTR + kb + t * 2 + 8);
                    bl[0] = *(const uint32_t*)(WL + n * ASTR + kb + t * 2);
                    bl[1] = *(const uint32_t*)(WL + n * ASTR + kb + t * 2 + 8);
                    mma16816(acc[w][nb], ah, bh);
                    mma16816(acc[w][nb], ah, bl);
                    mma16816(acc[w][nb], al, bh);
                }
            }
        }
    }

    {
        int row_a = m0 + r0 + g;
        int row_b = row_a + 8;
        #pragma unroll
        for (int w = 0; w < 3; w++) {
            float* dst = (w == 0) ? g_q : (w == 1) ? g_k : g_v;
            #pragma unroll
            for (int nb = 0; nb < 8; nb++) {
                int col = nb * 8 + t * 2;
                float b0 = biasS[w * 64 + col], b1 = biasS[w * 64 + col + 1];
                float2 v0 = { acc[w][nb][0] + b0, acc[w][nb][1] + b1 };
                float2 v1 = { acc[w][nb][2] + b0, acc[w][nb][3] + b1 };
                *(float2*)(dst + (size_t)row_a * DOUT + col) = v0;
                *(float2*)(dst + (size_t)row_b * DOUT + col) = v1;
            }
        }
    }
}

// ---------------------------------------------------------------------------
// HMMA flash attention, bf16x3 split on QK^T and PV, exp on FMA pipe.
// 128 CTAs (16 per batch) x 256 thr (8 warps). Warp owns 16 query rows.
// K smem [key][d] (B-frag for S); V smem transposed [d][key] (B-frag for PV),
// filled with a key-major thread map so transpose stores are only 2-way
// conflicted (d-major map was 8-way).
// ---------------------------------------------------------------------------
#define KSTR 72

__global__ void __launch_bounds__(256) attn_mma(float* __restrict__ out)
{
    __shared__ __nv_bfloat16 Ksh[64 * KSTR];
    __shared__ __nv_bfloat16 Ksl[64 * KSTR];
    __shared__ __nv_bfloat16 Vsh[64 * KSTR];
    __shared__ __nv_bfloat16 Vsl[64 * KSTR];
    __shared__ unsigned char maskS[64];

    int tid = threadIdx.x, wid = tid >> 5, lane = tid & 31;
    int g = lane >> 2, t = lane & 3;
    int b = blockIdx.x >> 4;
    int q0 = (blockIdx.x & 15) * 128;
    int qrow = q0 + wid * 16 + g;               // row "g"; +8 = second row

    const float scale = rsqrtf((float)SS);      // reference divides by sqrt(S)

    // Q fragments in registers (scaled, hi/lo split). a0=(g,klo) a1=(g+8,klo)
    // a2=(g,khi) a3=(g+8,khi)
    uint32_t qh[4][4], ql[4][4];
    {
        const float* gq = g_q + ((size_t)b * SS + qrow) * DOUT;
        #pragma unroll
        for (int ks = 0; ks < 4; ks++)
            #pragma unroll
            for (int hh = 0; hh < 2; hh++)
                #pragma unroll
                for (int rr = 0; rr < 2; rr++) {
                    float2 v = *(const float2*)(gq + (size_t)rr * 8 * DOUT + ks * 16 + hh * 8 + 2 * t);
                    float x0 = v.x * scale, x1 = v.y * scale;
                    __nv_bfloat16 h0 = __float2bfloat16(x0), h1 = __float2bfloat16(x1);
                    __nv_bfloat16 l0 = __float2bfloat16(x0 - __bfloat162float(h0));
                    __nv_bfloat16 l1 = __float2bfloat16(x1 - __bfloat162float(h1));
                    qh[ks][hh * 2 + rr] = bpack(h0, h1);
                    ql[ks][hh * 2 + rr] = bpack(l0, l1);
                }
    }

    float Ov[8][4];
    #pragma unroll
    for (int nb = 0; nb < 8; nb++)
        #pragma unroll
        for (int i = 0; i < 4; i++) Ov[nb][i] = 0.0f;
    float m_g = -1e30f, m_g8 = -1e30f, l_g = 0.0f, l_g8 = 0.0f;

    for (int kb0 = 0; kb0 < SS; kb0 += 64) {
        __syncthreads();

        // K fill: [key][d], d-major threads (coalesced loads, uint2 stores)
        #pragma unroll
        for (int it = 0; it < 4; it++) {
            int idx = it * 256 + tid;
            int key = idx >> 4;
            int d = (idx & 15) << 2;
            const float* gk = g_k + ((size_t)b * SS + kb0 + key) * DOUT + d;
            float4 kv = *(const float4*)gk;
            __nv_bfloat16 kh0 = __float2bfloat16(kv.x), kh1 = __float2bfloat16(kv.y);
            __nv_bfloat16 kh2 = __float2bfloat16(kv.z), kh3 = __float2bfloat16(kv.w);
            __nv_bfloat16 kl0 = __float2bfloat16(kv.x - __bfloat162float(kh0));
            __nv_bfloat16 kl1 = __float2bfloat16(kv.y - __bfloat162float(kh1));
            __nv_bfloat16 kl2 = __float2bfloat16(kv.z - __bfloat162float(kh2));
            __nv_bfloat16 kl3 = __float2bfloat16(kv.w - __bfloat162float(kh3));
            uint2 khv = { bpack(kh0, kh1), bpack(kh2, kh3) };
            uint2 klv = { bpack(kl0, kl1), bpack(kl2, kl3) };
            *(uint2*)(Ksh + key * KSTR + d) = khv;
            *(uint2*)(Ksl + key * KSTR + d) = klv;
        }

        // V fill: transposed [d][key], key-major threads so the strided
        // transpose stores hit 16 banks (2-way) instead of 2 banks (8-way).
        // K/V chunk is shared by the 16 CTAs of this batch -> L2-resident.
        #pragma unroll
        for (int it = 0; it < 4; it++) {
            int idx = it * 256 + tid;
            int key = idx & 63;
            int d = (idx >> 6) << 2;            // covers d = 0..60 over 4 its
            const float* gv = g_v + ((size_t)b * SS + kb0 + key) * DOUT + d;
            float4 vv = *(const float4*)gv;
            __nv_bfloat16 vh0 = __float2bfloat16(vv.x), vh1 = __float2bfloat16(vv.y);
            __nv_bfloat16 vh2 = __float2bfloat16(vv.z), vh3 = __float2bfloat16(vv.w);
            __nv_bfloat16 vl0 = __float2bfloat16(vv.x - __bfloat162float(vh0));
            __nv_bfloat16 vl1 = __float2bfloat16(vv.y - __bfloat162float(vh1));
            __nv_bfloat16 vl2 = __float2bfloat16(vv.z - __bfloat162float(vh2));
            __nv_bfloat16 vl3 = __float2bfloat16(vv.w - __bfloat162float(vh3));
            Vsh[(d + 0) * KSTR + key] = vh0;  Vsl[(d + 0) * KSTR + key] = vl0;
            Vsh[(d + 1) * KSTR + key] = vh1;  Vsl[(d + 1) * KSTR + key] = vl1;
            Vsh[(d + 2) * KSTR + key] = vh2;  Vsl[(d + 2) * KSTR + key] = vl2;
            Vsh[(d + 3) * KSTR + key] = vh3;  Vsl[(d + 3) * KSTR + key] = vl3;
        }
        if (tid < 64) maskS[tid] = g_mask[b * SS + kb0 + tid];
        __syncthreads();

        // S = Q K^T (3-term split), C-frags sc[nb]: cols = keys nb*8+{2t,2t+1}
        float sc[8][4];
        #pragma unroll
        for (int nb = 0; nb < 8; nb++)
            #pragma unroll
            for (int i = 0; i < 4; i++) sc[nb][i] = 0.0f;

        #pragma unroll
        for (int ks = 0; ks < 4; ks++) {
            int kb = ks * 16;
            #pragma unroll
            for (int nb = 0; nb < 8; nb++) {
                int n = nb * 8 + g;
                const __nv_bfloat16* KH = Ksh + n * KSTR + kb + 2 * t;
                const __nv_bfloat16* KL = Ksl + n * KSTR + kb + 2 * t;
                uint32_t bh[2] = { *(const uint32_t*)KH, *(const uint32_t*)(KH + 8) };
                uint32_t bl[2] = { *(const uint32_t*)KL, *(const uint32_t*)(KL + 8) };
                mma16816(sc[nb], qh[ks], bh);
                mma16816(sc[nb], qh[ks], bl);
                mma16816(sc[nb], ql[ks], bh);
            }
        }

        // Mask (exactly -1e9, as in reference)
        #pragma unroll
        for (int nb = 0; nb < 8; nb++) {
            int c0 = nb * 8 + 2 * t;
            if (maskS[c0])     { sc[nb][0] = -1e9f; sc[nb][2] = -1e9f; }
            if (maskS[c0 + 1]) { sc[nb][1] = -1e9f; sc[nb][3] = -1e9f; }
        }

        // Row maxima (reduce over the 4 t-threads of each row)
        float rmg = -1e30f, rmg8 = -1e30f;
        #pragma unroll
        for (int nb = 0; nb < 8; nb++) {
            rmg  = fmaxf(rmg,  fmaxf(sc[nb][0], sc[nb][1]));
            rmg8 = fmaxf(rmg8, fmaxf(sc[nb][2], sc[nb][3]));
        }
        rmg  = fmaxf(rmg,  __shfl_xor_sync(0xffffffffu, rmg, 1));
        rmg  = fmaxf(rmg,  __shfl_xor_sync(0xffffffffu, rmg, 2));
        rmg8 = fmaxf(rmg8, __shfl_xor_sync(0xffffffffu, rmg8, 1));
        rmg8 = fmaxf(rmg8, __shfl_xor_sync(0xffffffffu, rmg8, 2));

        float mn_g = fmaxf(m_g, rmg), mn_g8 = fmaxf(m_g8, rmg8);
        float fct_g = exp_fma(m_g - mn_g), fct_g8 = exp_fma(m_g8 - mn_g8);
        m_g = mn_g; m_g8 = mn_g8;

        // P = exp(S - m), split hi/lo, repack C-frag -> A-frag (register-local)
        uint32_t pah[4][4], pal[4][4];
        float sl_g = 0.0f, sl_g8 = 0.0f;
        #pragma unroll
        for (int nb = 0; nb < 8; nb++) {
            float p0 = exp_fma(sc[nb][0] - mn_g);
            float p1 = exp_fma(sc[nb][1] - mn_g);
            float p2 = exp_fma(sc[nb][2] - mn_g8);
            float p3 = exp_fma(sc[nb][3] - mn_g8);
            sl_g += p0 + p1;  sl_g8 += p2 + p3;
            __nv_bfloat16 h0 = __float2bfloat16(p0), h1 = __float2bfloat16(p1);
            __nv_bfloat16 h2 = __float2bfloat16(p2), h3 = __float2bfloat16(p3);
            __nv_bfloat16 L0 = __float2bfloat16(p0 - __bfloat162float(h0));
            __nv_bfloat16 L1 = __float2bfloat16(p1 - __bfloat162float(h1));
            __nv_bfloat16 L2 = __float2bfloat16(p2 - __bfloat162float(h2));
            __nv_bfloat16 L3 = __float2bfloat16(p3 - __bfloat162float(h3));
            int kc = nb >> 1, hi = nb & 1;
            pah[kc][hi * 2 + 0] = bpack(h0, h1);   // row g
            pah[kc][hi * 2 + 1] = bpack(h2, h3);   // row g+8
            pal[kc][hi * 2 + 0] = bpack(L0, L1);
            pal[kc][hi * 2 + 1] = bpack(L2, L3);
        }
        sl_g  += __shfl_xor_sync(0xffffffffu, sl_g, 1);
        sl_g  += __shfl_xor_sync(0xffffffffu, sl_g, 2);
        sl_g8 += __shfl_xor_sync(0xffffffffu, sl_g8, 1);
        sl_g8 += __shfl_xor_sync(0xffffffffu, sl_g8, 2);
        l_g  = l_g  * fct_g  + sl_g;
        l_g8 = l_g8 * fct_g8 + sl_g8;

        // Rescale O, then O += P V (3-term split)
        #pragma unroll
        for (int nb = 0; nb < 8; nb++) {
            Ov[nb][0] *= fct_g;  Ov[nb][1] *= fct_g;
            Ov[nb][2] *= fct_g8; Ov[nb][3] *= fct_g8;
        }
        #pragma unroll
        for (int kc = 0; kc < 4; kc++) {
            int kb = kc * 16;
            #pragma unroll
            for (int nb = 0; nb < 8; nb++) {
                int n = nb * 8 + g;
                const __nv_bfloat16* VH = Vsh + n * KSTR + kb + 2 * t;
                const __nv_bfloat16* VL = Vsl + n * KSTR + kb + 2 * t;
                uint32_t vbh[2] = { *(const uint32_t*)VH, *(const uint32_t*)(VH + 8) };
                uint32_t vbl[2] = { *(const uint32_t*)VL, *(const uint32_t*)(VL + 8) };
                mma16816(Ov[nb], pah[kc], vbh);
                mma16816(Ov[nb], pah[kc], vbl);
                mma16816(Ov[nb], pal[kc], vbh);
            }
        }
    }

    // Epilogue
    float il_g = 1.0f / l_g, il_g8 = 1.0f / l_g8;
    float* po = out + ((size_t)b * SS + qrow) * DOUT;
    #pragma unroll
    for (int nb = 0; nb < 8; nb++) {
        int d = nb * 8 + 2 * t;
        float2 v0 = { Ov[nb][0] * il_g,  Ov[nb][1] * il_g  };
        float2 v1 = { Ov[nb][2] * il_g8, Ov[nb][3] * il_g8 };
        *(float2*)(po + d) = v0;
        *(float2*)(po + (size_t)8 * DOUT + d) = v1;
    }
}

// ---------------------------------------------------------------------------
extern "C" void kernel_launch(void* const* d_in, const int* in_sizes, int n_in,
                              void* d_out, int out_size)
{
    const float* seq = (const float*)d_in[0];
    const unsigned char* mask = (const unsigned char*)d_in[1];
    const float* Wq = (const float*)d_in[2];
    const float* bq = (const float*)d_in[3];
    const float* Wk = (const float*)d_in[4];
    const float* bk = (const float*)d_in[5];
    const float* Wv = (const float*)d_in[6];
    const float* bv = (const float*)d_in[7];
    float* out = (float*)d_out;

    w_convert<<<192, 256>>>(Wq, Wk, Wv);

    cudaFuncSetAttribute(proj_mma, cudaFuncAttributeMaxDynamicSharedMemorySize, PJ_SMEM);
    proj_mma<<<128, 256, PJ_SMEM>>>(seq, mask, bq, bk, bv);

    attn_mma<<<128, 256>>>(out);
}

// round 16
// speedup vs baseline: 2.5348x; 1.2189x over previous
#include <cuda_runtime.h>
#include <cuda_bf16.h>
#include <cstdint>

#define BB 8
#define SS 2048
#define DIN 1024
#define DOUT 64

// Scratch (device globals: no allocation allowed)
__device__ unsigned char g_mask[BB * SS];
// Pre-converted activations (written by proj_mma epilogue):
__device__ __align__(16) __nv_bfloat16 g_qb[BB * SS * DOUT];   // q * 1/sqrt(S), bf16
__device__ __align__(16) __nv_bfloat16 g_kb[BB * SS * DOUT];   // k, bf16
__device__ __align__(16) __nv_bfloat16 g_vth[BB * DOUT * SS];  // v hi, transposed [b][d][s]
__device__ __align__(16) __nv_bfloat16 g_vtl[BB * DOUT * SS];  // v lo, transposed
// W transposed + bf16 hi/lo split: [w][n][k]
__device__ __align__(16) __nv_bfloat16 g_wh[3 * DOUT * DIN];
__device__ __align__(16) __nv_bfloat16 g_wl[3 * DOUT * DIN];

// ---------------------------------------------------------------------------
// Helpers
// ---------------------------------------------------------------------------
__device__ __forceinline__ uint32_t bpack(__nv_bfloat16 a, __nv_bfloat16 b) {
    return ((uint32_t)__bfloat16_as_ushort(b) << 16) | __bfloat16_as_ushort(a);
}

// mma.sync m16n8k16 row.col f32 += bf16*bf16 (baseline PTX ISA, sm_80+)
__device__ __forceinline__ void mma16816(float* c, const uint32_t* a, const uint32_t* b) {
    asm volatile(
        "mma.sync.aligned.m16n8k16.row.col.f32.bf16.bf16.f32 "
        "{%0,%1,%2,%3}, {%4,%5,%6,%7}, {%8,%9}, {%0,%1,%2,%3};"
        : "+f"(c[0]), "+f"(c[1]), "+f"(c[2]), "+f"(c[3])
        : "r"(a[0]), "r"(a[1]), "r"(a[2]), "r"(a[3]), "r"(b[0]), "r"(b[1]));
}

// exp(x) for x <= 0 on the FMA/ALU pipes (no MUFU). rel err ~2e-6.
__device__ __forceinline__ float exp_fma(float x) {
    x = fmaxf(x, -87.0f);
    float t  = fmaf(x, 1.4426950408889634f, 12582912.0f);
    float fi = t - 12582912.0f;
    float f  = fmaf(x, 1.4426950408889634f, -fi);
    float p  = 0.0013333558f;
    p = fmaf(p, f, 0.0096181291f);
    p = fmaf(p, f, 0.0555041087f);
    p = fmaf(p, f, 0.2402265069f);
    p = fmaf(p, f, 0.6931471806f);
    p = fmaf(p, f, 1.0f);
    int ei = (__float_as_int(t) & 0x7FFFFF) - 0x400000;
    return __int_as_float((ei + 127) << 23) * p;
}

// ---------------------------------------------------------------------------
// W prep: transpose + bf16 hi/lo split. 768 blocks -> 1 element per thread.
// ---------------------------------------------------------------------------
__global__ void w_convert(const float* __restrict__ Wq, const float* __restrict__ Wk,
                          const float* __restrict__ Wv) {
    int i = blockIdx.x * blockDim.x + threadIdx.x;
    if (i >= 3 * DIN * DOUT) return;
    int w = i / (DIN * DOUT);
    int r = i - w * (DIN * DOUT);
    int k = r / DOUT, n = r % DOUT;
    const float* W = (w == 0) ? Wq : (w == 1) ? Wk : Wv;
    float x = W[r];
    __nv_bfloat16 h = __float2bfloat16(x);
    __nv_bfloat16 l = __float2bfloat16(x - __bfloat162float(h));
    g_wh[w * DIN * DOUT + n * DIN + k] = h;
    g_wl[w * DIN * DOUT + n * DIN + k] = l;
}

// ---------------------------------------------------------------------------
// HMMA QKV projection (bf16x3 split). 128 CTAs x 256 thr, M_tile=128.
// Epilogue emits pre-converted bf16 activations (q scaled, v split+transposed).
// CTA 0 folds in mask normalization.
// ---------------------------------------------------------------------------
#define ASTR 72
#define SM_AH 0
#define SM_AL (128 * ASTR * 2)
#define SM_W  (2 * 128 * ASTR * 2)
#define SM_BIAS (SM_W + 6 * 64 * ASTR * 2)
#define PJ_SMEM (SM_BIAS + 768)

__global__ void __launch_bounds__(256) proj_mma(
    const float* __restrict__ A, const unsigned char* __restrict__ maskp,
    const float* __restrict__ bq, const float* __restrict__ bk, const float* __restrict__ bv)
{
    extern __shared__ unsigned char smem[];
    __nv_bfloat16* AH = (__nv_bfloat16*)(smem + SM_AH);
    __nv_bfloat16* AL = (__nv_bfloat16*)(smem + SM_AL);
    float* biasS = (float*)(smem + SM_BIAS);

    int tid = threadIdx.x, wid = tid >> 5, lane = tid & 31;
    int g = lane >> 2, t = lane & 3;
    int m0 = blockIdx.x * 128;
    int r0 = wid * 16;

    if (blockIdx.x == 0) {
        __shared__ int s_off, s_al;
        if (tid == 0) { s_off = 0; s_al = 0; }
        __syncthreads();
        int lo = 0, la = 0;
        for (int i = tid; i < BB * SS; i += 256) {
            unsigned char v = maskp[i];
            if (v) { if (i & 3) lo++; else la++; }
        }
        if (lo) atomicAdd(&s_off, lo);
        if (la) atomicAdd(&s_al, la);
        __syncthreads();
        int kind = 0;
        if (s_off == 0 && s_al > 0) kind = 1;
        else if (s_al == 0 && s_off > 0) kind = 2;
        for (int i = tid; i < BB * SS; i += 256) {
            unsigned char m;
            if (kind == 1)      m = (((const int*)(const void*)maskp)[i] != 0);
            else if (kind == 2) m = (((const float*)(const void*)maskp)[i] != 0.0f);
            else                m = (maskp[i] != 0);
            g_mask[i] = m;
        }
    }

    if (tid < 64) {
        biasS[tid]       = bq[tid];
        biasS[tid + 64]  = bk[tid];
        biasS[tid + 128] = bv[tid];
    }

    float acc[3][8][4];
    #pragma unroll
    for (int w = 0; w < 3; w++)
        #pragma unroll
        for (int nb = 0; nb < 8; nb++)
            #pragma unroll
            for (int i = 0; i < 4; i++) acc[w][nb][i] = 0.0f;

    for (int c = 0; c < 16; c++) {
        int k0 = c * 64;
        __syncthreads();

        #pragma unroll
        for (int it = 0; it < 8; it++) {
            int idx = it * 256 + tid;
            int row = idx >> 4;
            int col = (idx & 15) << 2;
            float4 v = *(const float4*)(A + (size_t)(m0 + row) * DIN + k0 + col);
            __nv_bfloat16 h0 = __float2bfloat16(v.x), h1 = __float2bfloat16(v.y);
            __nv_bfloat16 h2 = __float2bfloat16(v.z), h3 = __float2bfloat16(v.w);
            __nv_bfloat16 l0 = __float2bfloat16(v.x - __bfloat162float(h0));
            __nv_bfloat16 l1 = __float2bfloat16(v.y - __bfloat162float(h1));
            __nv_bfloat16 l2 = __float2bfloat16(v.z - __bfloat162float(h2));
            __nv_bfloat16 l3 = __float2bfloat16(v.w - __bfloat162float(h3));
            uint2 hv = { bpack(h0, h1), bpack(h2, h3) };
            uint2 lv = { bpack(l0, l1), bpack(l2, l3) };
            *(uint2*)(AH + row * ASTR + col) = hv;
            *(uint2*)(AL + row * ASTR + col) = lv;
        }

        #pragma unroll
        for (int it = 0; it < 24; it++) {
            int i = it * 256 + tid;
            int tile = i >> 10;
            int word = i & 1023;
            int n = word >> 4;
            int kk = (word & 15) << 2;
            const __nv_bfloat16* src = (tile & 1) ? g_wl : g_wh;
            uint2 d = *(const uint2*)(src + (size_t)(tile >> 1) * (DIN * DOUT) + n * DIN + k0 + kk);
            *(uint2*)((__nv_bfloat16*)(smem + SM_W) + tile * (64 * ASTR) + n * ASTR + kk) = d;
        }
        __syncthreads();

        #pragma unroll
        for (int ks = 0; ks < 4; ks++) {
            int kb = ks * 16;
            uint32_t ah[4], al[4];
            ah[0] = *(const uint32_t*)(AH + (r0 + g)     * ASTR + kb + t * 2);
            ah[1] = *(const uint32_t*)(AH + (r0 + g + 8) * ASTR + kb + t * 2);
            ah[2] = *(const uint32_t*)(AH + (r0 + g)     * ASTR + kb + t * 2 + 8);
            ah[3] = *(const uint32_t*)(AH + (r0 + g + 8) * ASTR + kb + t * 2 + 8);
            al[0] = *(const uint32_t*)(AL + (r0 + g)     * ASTR + kb + t * 2);
            al[1] = *(const uint32_t*)(AL + (r0 + g + 8) * ASTR + kb + t * 2);
            al[2] = *(const uint32_t*)(AL + (r0 + g)     * ASTR + kb + t * 2 + 8);
            al[3] = *(const uint32_t*)(AL + (r0 + g + 8) * ASTR + kb + t * 2 + 8);

            #pragma unroll
            for (int w = 0; w < 3; w++) {
                const __nv_bfloat16* WH = (__nv_bfloat16*)(smem + SM_W) + (w * 2)     * (64 * ASTR);
                const __nv_bfloat16* WL = (__nv_bfloat16*)(smem + SM_W) + (w * 2 + 1) * (64 * ASTR);
                #pragma unroll
                for (int nb = 0; nb < 8; nb++) {
                    int n = nb * 8 + g;
                    uint32_t bh[2], bl[2];
                    bh[0] = *(const uint32_t*)(WH + n * ASTR + kb + t * 2);
                    bh[1] = *(const uint32_t*)(WH + n * ASTR + kb + t * 2 + 8);
                    bl[0] = *(const uint32_t*)(WL + n * ASTR + kb + t * 2);
                    bl[1] = *(const uint32_t*)(WL + n * ASTR + kb + t * 2 + 8);
                    mma16816(acc[w][nb], ah, bh);
                    mma16816(acc[w][nb], ah, bl);
                    mma16816(acc[w][nb], al, bh);
                }
            }
        }
    }

    // ---- Epilogue: bias add, convert to bf16, q scaled, v split+transposed ----
    {
        const float qs = rsqrtf((float)SS);
        int row_a = m0 + r0 + g;
        int row_b = row_a + 8;
        int bb = row_a >> 11;
        int sa = row_a & (SS - 1), sb = sa + 8;
        #pragma unroll
        for (int nb = 0; nb < 8; nb++) {
            int col = nb * 8 + t * 2;
            // q (scaled)
            float q0 = (acc[0][nb][0] + biasS[col])     * qs;
            float q1 = (acc[0][nb][1] + biasS[col + 1]) * qs;
            float q2 = (acc[0][nb][2] + biasS[col])     * qs;
            float q3 = (acc[0][nb][3] + biasS[col + 1]) * qs;
            *(uint32_t*)(g_qb + (size_t)row_a * DOUT + col) =
                bpack(__float2bfloat16(q0), __float2bfloat16(q1));
            *(uint32_t*)(g_qb + (size_t)row_b * DOUT + col) =
                bpack(__float2bfloat16(q2), __float2bfloat16(q3));
            // k
            float k0v = acc[1][nb][0] + biasS[64 + col];
            float k1v = acc[1][nb][1] + biasS[64 + col + 1];
            float k2v = acc[1][nb][2] + biasS[64 + col];
            float k3v = acc[1][nb][3] + biasS[64 + col + 1];
            *(uint32_t*)(g_kb + (size_t)row_a * DOUT + col) =
                bpack(__float2bfloat16(k0v), __float2bfloat16(k1v));
            *(uint32_t*)(g_kb + (size_t)row_b * DOUT + col) =
                bpack(__float2bfloat16(k2v), __float2bfloat16(k3v));
            // v: hi/lo split, transposed [b][d][s]
            float v0 = acc[2][nb][0] + biasS[128 + col];
            float v1 = acc[2][nb][1] + biasS[128 + col + 1];
            float v2 = acc[2][nb][2] + biasS[128 + col];
            float v3 = acc[2][nb][3] + biasS[128 + col + 1];
            __nv_bfloat16 vh0 = __float2bfloat16(v0), vh1 = __float2bfloat16(v1);
            __nv_bfloat16 vh2 = __float2bfloat16(v2), vh3 = __float2bfloat16(v3);
            __nv_bfloat16 vl0 = __float2bfloat16(v0 - __bfloat162float(vh0));
            __nv_bfloat16 vl1 = __float2bfloat16(v1 - __bfloat162float(vh1));
            __nv_bfloat16 vl2 = __float2bfloat16(v2 - __bfloat162float(vh2));
            __nv_bfloat16 vl3 = __float2bfloat16(v3 - __bfloat162float(vh3));
            size_t c0 = ((size_t)bb * DOUT + col) * SS;
            size_t c1 = ((size_t)bb * DOUT + col + 1) * SS;
            g_vth[c0 + sa] = vh0;  g_vtl[c0 + sa] = vl0;
            g_vth[c1 + sa] = vh1;  g_vtl[c1 + sa] = vl1;
            g_vth[c0 + sb] = vh2;  g_vtl[c0 + sb] = vl2;
            g_vth[c1 + sb] = vh3;  g_vtl[c1 + sb] = vl3;
        }
    }
}

// ---------------------------------------------------------------------------
// HMMA flash attention. Q/K plain bf16 (single-term S: scores tiny after the
// 1/sqrt(S) scale, so bf16 rounding costs ~2e-4 rel in context). PV keeps the
// bf16x3 split. All fills are pure coalesced copies of pre-converted data.
// 128 CTAs (16 per batch) x 256 thr (8 warps). Warp owns 16 query rows.
// ---------------------------------------------------------------------------
#define KSTR 72

__global__ void __launch_bounds__(256) attn_mma(float* __restrict__ out)
{
    __shared__ __nv_bfloat16 Ksh[64 * KSTR];
    __shared__ __nv_bfloat16 Vsh[64 * KSTR];
    __shared__ __nv_bfloat16 Vsl[64 * KSTR];
    __shared__ unsigned char maskS[64];

    int tid = threadIdx.x, wid = tid >> 5, lane = tid & 31;
    int g = lane >> 2, t = lane & 3;
    int b = blockIdx.x >> 4;
    int q0 = (blockIdx.x & 15) * 128;
    int qrow = q0 + wid * 16 + g;

    // Q fragments (already scaled bf16 in gmem)
    uint32_t qh[4][4];
    {
        const __nv_bfloat16* gq = g_qb + ((size_t)b * SS + qrow) * DOUT;
        #pragma unroll
        for (int ks = 0; ks < 4; ks++)
            #pragma unroll
            for (int hh = 0; hh < 2; hh++)
                #pragma unroll
                for (int rr = 0; rr < 2; rr++)
                    qh[ks][hh * 2 + rr] = *(const uint32_t*)(gq + (size_t)rr * 8 * DOUT +
                                                             ks * 16 + hh * 8 + 2 * t);
    }

    float Ov[8][4];
    #pragma unroll
    for (int nb = 0; nb < 8; nb++)
        #pragma unroll
        for (int i = 0; i < 4; i++) Ov[nb][i] = 0.0f;
    float m_g = -1e30f, m_g8 = -1e30f, l_g = 0.0f, l_g8 = 0.0f;

    for (int kb0 = 0; kb0 < SS; kb0 += 64) {
        __syncthreads();

        // K fill: straight uint2 copy (4 per thread), [key][d]
        #pragma unroll
        for (int it = 0; it < 4; it++) {
            int idx = it * 256 + tid;
            int key = idx >> 4;
            int dp = (idx & 15) << 2;
            uint2 d = *(const uint2*)(g_kb + ((size_t)b * SS + kb0 + key) * DOUT + dp);
            *(uint2*)(Ksh + key * KSTR + dp) = d;
        }
        // V fill: straight uint32 copies from transposed gmem, [d][key]
        #pragma unroll
        for (int it = 0; it < 8; it++) {
            int idx = it * 256 + tid;
            int d = idx >> 5;
            int kp = (idx & 31) << 1;
            size_t go = ((size_t)b * DOUT + d) * SS + kb0 + kp;
            *(uint32_t*)(Vsh + d * KSTR + kp) = *(const uint32_t*)(g_vth + go);
            *(uint32_t*)(Vsl + d * KSTR + kp) = *(const uint32_t*)(g_vtl + go);
        }
        if (tid < 64) maskS[tid] = g_mask[b * SS + kb0 + tid];
        __syncthreads();

        // S = Q K^T (single term, plain bf16)
        float sc[8][4];
        #pragma unroll
        for (int nb = 0; nb < 8; nb++)
            #pragma unroll
            for (int i = 0; i < 4; i++) sc[nb][i] = 0.0f;

        #pragma unroll
        for (int ks = 0; ks < 4; ks++) {
            int kb = ks * 16;
            #pragma unroll
            for (int nb = 0; nb < 8; nb++) {
                int n = nb * 8 + g;
                const __nv_bfloat16* KH = Ksh + n * KSTR + kb + 2 * t;
                uint32_t bh[2] = { *(const uint32_t*)KH, *(const uint32_t*)(KH + 8) };
                mma16816(sc[nb], qh[ks], bh);
            }
        }

        // Mask (exactly -1e9, as in reference)
        #pragma unroll
        for (int nb = 0; nb < 8; nb++) {
            int c0 = nb * 8 + 2 * t;
            if (maskS[c0])     { sc[nb][0] = -1e9f; sc[nb][2] = -1e9f; }
            if (maskS[c0 + 1]) { sc[nb][1] = -1e9f; sc[nb][3] = -1e9f; }
        }

        // Row maxima (reduce over 4 t-threads)
        float rmg = -1e30f, rmg8 = -1e30f;
        #pragma unroll
        for (int nb = 0; nb < 8; nb++) {
            rmg  = fmaxf(rmg,  fmaxf(sc[nb][0], sc[nb][1]));
            rmg8 = fmaxf(rmg8, fmaxf(sc[nb][2], sc[nb][3]));
        }
        rmg  = fmaxf(rmg,  __shfl_xor_sync(0xffffffffu, rmg, 1));
        rmg  = fmaxf(rmg,  __shfl_xor_sync(0xffffffffu, rmg, 2));
        rmg8 = fmaxf(rmg8, __shfl_xor_sync(0xffffffffu, rmg8, 1));
        rmg8 = fmaxf(rmg8, __shfl_xor_sync(0xffffffffu, rmg8, 2));

        float mn_g = fmaxf(m_g, rmg), mn_g8 = fmaxf(m_g8, rmg8);
        float fct_g = exp_fma(m_g - mn_g), fct_g8 = exp_fma(m_g8 - mn_g8);
        m_g = mn_g; m_g8 = mn_g8;

        // P = exp(S - m) (FMA-pipe exp), hi/lo split, C-frag -> A-frag repack
        uint32_t pah[4][4], pal[4][4];
        float sl_g = 0.0f, sl_g8 = 0.0f;
        #pragma unroll
        for (int nb = 0; nb < 8; nb++) {
            float p0 = exp_fma(sc[nb][0] - mn_g);
            float p1 = exp_fma(sc[nb][1] - mn_g);
            float p2 = exp_fma(sc[nb][2] - mn_g8);
            float p3 = exp_fma(sc[nb][3] - mn_g8);
            sl_g += p0 + p1;  sl_g8 += p2 + p3;
            __nv_bfloat16 h0 = __float2bfloat16(p0), h1 = __float2bfloat16(p1);
            __nv_bfloat16 h2 = __float2bfloat16(p2), h3 = __float2bfloat16(p3);
            __nv_bfloat16 L0 = __float2bfloat16(p0 - __bfloat162float(h0));
            __nv_bfloat16 L1 = __float2bfloat16(p1 - __bfloat162float(h1));
            __nv_bfloat16 L2 = __float2bfloat16(p2 - __bfloat162float(h2));
            __nv_bfloat16 L3 = __float2bfloat16(p3 - __bfloat162float(h3));
            int kc = nb >> 1, hi = nb & 1;
            pah[kc][hi * 2 + 0] = bpack(h0, h1);
            pah[kc][hi * 2 + 1] = bpack(h2, h3);
            pal[kc][hi * 2 + 0] = bpack(L0, L1);
            pal[kc][hi * 2 + 1] = bpack(L2, L3);
        }
        sl_g  += __shfl_xor_sync(0xffffffffu, sl_g, 1);
        sl_g  += __shfl_xor_sync(0xffffffffu, sl_g, 2);
        sl_g8 += __shfl_xor_sync(0xffffffffu, sl_g8, 1);
        sl_g8 += __shfl_xor_sync(0xffffffffu, sl_g8, 2);
        l_g  = l_g  * fct_g  + sl_g;
        l_g8 = l_g8 * fct_g8 + sl_g8;

        // O = O*fct + P V (3-term split: ph*vh + ph*vl + pl*vh)
        #pragma unroll
        for (int nb = 0; nb < 8; nb++) {
            Ov[nb][0] *= fct_g;  Ov[nb][1] *= fct_g;
            Ov[nb][2] *= fct_g8; Ov[nb][3] *= fct_g8;
        }
        #pragma unroll
        for (int kc = 0; kc < 4; kc++) {
            int kb = kc * 16;
            #pragma unroll
            for (int nb = 0; nb < 8; nb++) {
                int n = nb * 8 + g;
                const __nv_bfloat16* VH = Vsh + n * KSTR + kb + 2 * t;
                const __nv_bfloat16* VL = Vsl + n * KSTR + kb + 2 * t;
                uint32_t vbh[2] = { *(const uint32_t*)VH, *(const uint32_t*)(VH + 8) };
                uint32_t vbl[2] = { *(const uint32_t*)VL, *(const uint32_t*)(VL + 8) };
                mma16816(Ov[nb], pah[kc], vbh);
                mma16816(Ov[nb], pah[kc], vbl);
                mma16816(Ov[nb], pal[kc], vbh);
            }
        }
    }

    // Epilogue
    float il_g = 1.0f / l_g, il_g8 = 1.0f / l_g8;
    float* po = out + ((size_t)b * SS + qrow) * DOUT;
    #pragma unroll
    for (int nb = 0; nb < 8; nb++) {
        int d = nb * 8 + 2 * t;
        float2 v0 = { Ov[nb][0] * il_g,  Ov[nb][1] * il_g  };
        float2 v1 = { Ov[nb][2] * il_g8, Ov[nb][3] * il_g8 };
        *(float2*)(po + d) = v0;
        *(float2*)(po + (size_t)8 * DOUT + d) = v1;
    }
}

// ---------------------------------------------------------------------------
extern "C" void kernel_launch(void* const* d_in, const int* in_sizes, int n_in,
                              void* d_out, int out_size)
{
    const float* seq = (const float*)d_in[0];
    const unsigned char* mask = (const unsigned char*)d_in[1];
    const float* Wq = (const float*)d_in[2];
    const float* bq = (const float*)d_in[3];
    const float* Wk = (const float*)d_in[4];
    const float* bk = (const float*)d_in[5];
    const float* Wv = (const float*)d_in[6];
    const float* bv = (const float*)d_in[7];
    float* out = (float*)d_out;

    w_convert<<<768, 256>>>(Wq, Wk, Wv);

    cudaFuncSetAttribute(proj_mma, cudaFuncAttributeMaxDynamicSharedMemorySize, PJ_SMEM);
    proj_mma<<<128, 256, PJ_SMEM>>>(seq, mask, bq, bk, bv);

    attn_mma<<<128, 256>>>(out);
}